// round 16
// baseline (speedup 1.0000x reference)
#include <cuda_runtime.h>
#include <cuda_bf16.h>

// Problem constants (fixed by the dataset builder)
#define BB    64          // batches
#define SS    4096        // spikes per batch
#define LL    25          // Lmax
#define NBINS 3600        // OH*OW
#define CAPC  128         // cap
#define NC    64          // chunks per batch
#define CHUNK (SS / NC)   // 64 spikes per chunk
#define NSC   16          // superchunks of 256 spikes (4 chunks) for packed count
#define OFFCLAMP 160u     // offsets >= 128 are dead; clamp keeps u8 exact where live

// Scratch (static device globals — allocation-free per harness rules)
// g_counts[b][sc][bin]: 4 chunks' counts in the 4 byte fields (each <= 64).
__device__ unsigned int  g_counts[BB * NSC * NBINS];          // 14.7 MB
__device__ unsigned char g_off[(size_t)BB * NC * NBINS];      // 14.7 MB, clamped u8

// ---------------------------------------------------------------------------
// Kernel 1: fill output with -1.0f (118 MB, DRAM roofline-bound).
// Streaming stores (evict-first) keep L2 free for indices/g_counts/g_off.
// ---------------------------------------------------------------------------
__global__ void fill_kernel(float4* __restrict__ out) {
    int i = blockIdx.x * blockDim.x + threadIdx.x;
    float4 v = make_float4(-1.0f, -1.0f, -1.0f, -1.0f);
    int base = i * 4;
    __stcs(&out[base + 0], v);
    __stcs(&out[base + 1], v);
    __stcs(&out[base + 2], v);
    __stcs(&out[base + 3], v);
}

// ---------------------------------------------------------------------------
// Kernel 2: packed per-chunk histogram. One block (256 thr = 8 warps) per
// superchunk of 256 spikes = 4 chunks of 64. Warps 2k,2k+1 count chunk k
// into byte field k (add = 1<<(8k)). Fields never exceed 64 -> no carry.
// ---------------------------------------------------------------------------
__global__ void count_kernel(const int* __restrict__ spikes,
                             const int* __restrict__ indices) {
    __shared__ unsigned int hist[NBINS];
    int tid = threadIdx.x;
    for (int i = tid; i < NBINS; i += 256) hist[i] = 0u;
    __syncthreads();

    int b  = blockIdx.x >> 4;   // NSC == 16
    int sc = blockIdx.x & 15;
    int warp = tid >> 5, lane = tid & 31;
    const int* sp = spikes + b * SS + sc * 256 + warp * 32;
    unsigned int add = 1u << (8 * (warp >> 1));

    for (int k = 0; k < 32; k++) {
        int id = __ldg(&sp[k]);                      // uniform broadcast load
        int j = -1;
        if (lane < LL) j = __ldg(&indices[id * LL + lane]);
        if (j >= 0) {
            unsigned int bin = (unsigned int)j % (unsigned int)NBINS;
            atomicAdd(&hist[bin], add);
        }
    }
    __syncthreads();

    unsigned int* dst = g_counts + (size_t)blockIdx.x * NBINS;
    for (int i = tid; i < NBINS; i += 256) dst[i] = hist[i];
}

// ---------------------------------------------------------------------------
// Kernel 3: exclusive scan over 64 chunks per (b,bin). One thread handles 4
// consecutive bins, composing each chunk's 4 u8 offsets into ONE u32 store.
// ---------------------------------------------------------------------------
__global__ void scan_kernel() {
    int idx = blockIdx.x * 256 + threadIdx.x;       // thread per 4 bins
    if (idx >= BB * (NBINS / 4)) return;
    int b  = idx / (NBINS / 4);
    int bq = idx - b * (NBINS / 4);
    int bin0 = bq * 4;

    unsigned int s0 = 0, s1 = 0, s2 = 0, s3 = 0;
#pragma unroll
    for (int sc = 0; sc < NSC; sc++) {
        const uint4* src = (const uint4*)(g_counts
                           + ((size_t)(b * NSC + sc)) * NBINS + bin0);
        uint4 v = __ldg(src);
#pragma unroll
        for (int sub = 0; sub < 4; sub++) {
            int c = sc * 4 + sub;
            unsigned int o0 = min(s0, OFFCLAMP);
            unsigned int o1 = min(s1, OFFCLAMP);
            unsigned int o2 = min(s2, OFFCLAMP);
            unsigned int o3 = min(s3, OFFCLAMP);
            unsigned int w = o0 | (o1 << 8) | (o2 << 16) | (o3 << 24);
            *(unsigned int*)(g_off + ((size_t)(b * NC + c)) * NBINS + bin0) = w;
            unsigned int sh = 8 * sub;
            s0 += (v.x >> sh) & 0xFFu;
            s1 += (v.y >> sh) & 0xFFu;
            s2 += (v.z >> sh) & 0xFFu;
            s3 += (v.w >> sh) & 0xFFu;
        }
    }
}

// ---------------------------------------------------------------------------
// Kernel 4: ordered scatter. One WARP per (b,chunk) of 64 spikes; 4 warps per
// block. U16 counters (7200 B/warp, 28.8 KB/block -> same 7 blocks/SM as u8
// champion) halve the smem bank-conflict degree of the counter RMW: the 5
// consecutive bins of a window row straddle words at degree 2 instead of 4.
// Output stores use __stcs (write-once, never re-read -> evict-first).
// Depth-8 gather pipeline; __syncwarp between spikes orders counter RMWs.
// ---------------------------------------------------------------------------
__global__ void scatter_kernel(const int* __restrict__ spikes,
                               const int* __restrict__ indices,
                               float* __restrict__ out) {
    __shared__ __align__(16) unsigned short cnt[4 * NBINS];   // 28.8 KB
    const unsigned int FULL = 0xffffffffu;
    int warp = threadIdx.x >> 5, lane = threadIdx.x & 31;
    int chunk = blockIdx.x * 4 + warp;
    int b = chunk >> 6;        // NC == 64
    int c = chunk & 63;

    // Preload u8 offsets, expand to u16 in smem (225 x uint4 -> 2x uint4).
    unsigned short* my = cnt + warp * NBINS;
    {
        const uint4* offv = (const uint4*)(g_off + (size_t)chunk * NBINS);
        uint4* myv = (uint4*)my;
        for (int i = lane; i < NBINS / 16; i += 32) {
            uint4 v = __ldg(&offv[i]);
            uint4 lo, hi;
            lo.x = __byte_perm(v.x, 0, 0x4140);
            lo.y = __byte_perm(v.x, 0, 0x4342);
            lo.z = __byte_perm(v.y, 0, 0x4140);
            lo.w = __byte_perm(v.y, 0, 0x4342);
            hi.x = __byte_perm(v.z, 0, 0x4140);
            hi.y = __byte_perm(v.z, 0, 0x4342);
            hi.z = __byte_perm(v.w, 0, 0x4140);
            hi.w = __byte_perm(v.w, 0, 0x4342);
            myv[2 * i]     = lo;
            myv[2 * i + 1] = hi;
        }
    }

    const int* sp = spikes + b * SS + c * CHUNK;
    int idlo = __ldg(&sp[lane]);        // spikes 0..31
    int idhi = __ldg(&sp[32 + lane]);   // spikes 32..63
    float* outb = out + (size_t)b * CAPC * NBINS;
    bool act = lane < LL;
    __syncwarp();

    #define GATHER(dst, s) do {                                              \
        int _id = ((s) < 32) ? __shfl_sync(FULL, idlo, (s))                  \
                             : __shfl_sync(FULL, idhi, (s) - 32);            \
        (dst) = act ? __ldg(&indices[_id * LL + lane]) : -1;                 \
    } while (0)

    #define PROCESS(jv) do {                                                 \
        if ((jv) >= 0) {                                                     \
            unsigned int ju  = (unsigned int)(jv);                           \
            unsigned int ckk = ju / (unsigned int)NBINS;                     \
            unsigned int bin = ju - ckk * (unsigned int)NBINS;               \
            unsigned int r = my[bin];                                        \
            my[bin] = (unsigned short)(r + 1u);                              \
            if (r < CAPC) __stcs(&outb[(size_t)r * NBINS + bin], (float)ckk);\
        }                                                                    \
        __syncwarp();                                                        \
    } while (0)

    #define PROCESS_LAST(jv) do {                                            \
        if ((jv) >= 0) {                                                     \
            unsigned int ju  = (unsigned int)(jv);                           \
            unsigned int ckk = ju / (unsigned int)NBINS;                     \
            unsigned int bin = ju - ckk * (unsigned int)NBINS;               \
            unsigned int r = my[bin];                                        \
            my[bin] = (unsigned short)(r + 1u);                              \
            if (r < CAPC) __stcs(&outb[(size_t)r * NBINS + bin], (float)ckk);\
        }                                                                    \
    } while (0)

    int a0, a1, a2, a3, b0, b1, b2, b3;
    GATHER(a0, 0); GATHER(a1, 1); GATHER(a2, 2); GATHER(a3, 3);
    GATHER(b0, 4); GATHER(b1, 5); GATHER(b2, 6); GATHER(b3, 7);

    #pragma unroll 4
    for (int g = 0; g < CHUNK / 4 - 2; g++) {
        int s = g * 4;
        int c0, c1, c2, c3;
        GATHER(c0, s + 8); GATHER(c1, s + 9);
        GATHER(c2, s + 10); GATHER(c3, s + 11);
        PROCESS(a0); PROCESS(a1); PROCESS(a2); PROCESS(a3);
        a0 = b0; a1 = b1; a2 = b2; a3 = b3;
        b0 = c0; b1 = c1; b2 = c2; b3 = c3;
    }
    PROCESS(a0); PROCESS(a1); PROCESS(a2); PROCESS(a3);
    PROCESS(b0); PROCESS(b1); PROCESS(b2); PROCESS_LAST(b3);

    #undef GATHER
    #undef PROCESS
    #undef PROCESS_LAST
}

// ---------------------------------------------------------------------------
extern "C" void kernel_launch(void* const* d_in, const int* in_sizes, int n_in,
                              void* d_out, int out_size) {
    const int* spikes  = (const int*)d_in[0];   // (64, 4096, 1, 1) int32
    const int* indices = (const int*)d_in[1];   // (131072, 25) int32
    float* out = (float*)d_out;                 // (64, 128, 60, 60) float32

    fill_kernel<<<7200, 256>>>((float4*)out);
    count_kernel<<<BB * NSC, 256>>>(spikes, indices);
    scan_kernel<<<(BB * (NBINS / 4) + 255) / 256, 256>>>();
    scatter_kernel<<<BB * NC / 4, 128>>>(spikes, indices, out);
}